// round 12
// baseline (speedup 1.0000x reference)
#include <cuda_runtime.h>
#include <math.h>
#include <float.h>

// RMSPELoss R12: scan = R9 (stream ceiling + logits pre-gather). Finish =
// 4 lanes/row, DIVERGENCE-FREE perm split: lane q owns perms with perm[0]=q;
// remaining-column selection via predicated FSELs (uniform code all lanes).

#define BATCH 131072
#define NC 181
#define PI_F 3.14159265358979323846f
#define TWOPI_F 6.283185307179586f
#define INV_TWOPI_F 0.15915494309189535f

#define TOTAL_INT4 (BATCH * NC / 4)                    // 5,931,008
#define SCAN_THREADS 256
#define SCAN_UNROLL 8
#define SCAN_BLOCKS (TOTAL_INT4 / (SCAN_THREADS * SCAN_UNROLL))   // 2896, exact
#define SCAN_STRIDE (SCAN_BLOCKS * SCAN_THREADS)                  // 741,376

#define FIN_THREADS 256
#define FIN_BLOCKS (BATCH * 4 / FIN_THREADS)           // 2048

__device__ double   g_acc;    // zero-init; reset by epilogue each call
__device__ unsigned g_done;   // zero-init; reset by epilogue each call
// 3 x 64-bit words per row (192 bits >= 181). Zero-init; finish re-zeroes
// every word it reads, so each graph replay starts clean.
__device__ unsigned long long g_bits[BATCH * 3];
// compact copy of logits[:, 0:4], written by scan every call (same values)
__device__ __align__(16) float4 g_doa[BATCH];

// ---------------- kernel 1: streaming scan + logits pre-gather ----------------
__global__ __launch_bounds__(SCAN_THREADS)
void rmspe_scan(const float* __restrict__ logits, const int* __restrict__ labels) {
    const int t = blockIdx.x * SCAN_THREADS + threadIdx.x;
    const int4* __restrict__ g4 = reinterpret_cast<const int4*>(labels);

    // front-batched independent label loads: MLP = 8, perfectly coalesced
    int4 v[SCAN_UNROLL];
    #pragma unroll
    for (int j = 0; j < SCAN_UNROLL; j++)
        v[j] = __ldcs(&g4[t + j * SCAN_STRIDE]);

    // compact logits pre-gather: first BATCH threads copy row t's 4 scalars.
    if (t < BATCH) {
        const float* lp = logits + (long)t * NC;
        float4 d;
        d.x = __ldg(lp);     d.y = __ldg(lp + 1);
        d.z = __ldg(lp + 2); d.w = __ldg(lp + 3);
        g_doa[t] = d;
    }

    #pragma unroll
    for (int j = 0; j < SCAN_UNROLL; j++) {
        int4 x = v[j];
        if ((x.x | x.y | x.z | x.w) != 0) {            // rare (~8.5% of int4s)
            int linear = (t + j * SCAN_STRIDE) * 4;
            int vals[4] = {x.x, x.y, x.z, x.w};
            #pragma unroll
            for (int k = 0; k < 4; k++) {
                if (vals[k] == 1) {
                    int l = linear + k;
                    int r = l / NC;                    // mul-shift by constant
                    int c = l - r * NC;
                    // result unused -> REDG (fire-and-forget, no return dep)
                    atomicOr(&g_bits[r * 3 + (c >> 6)], 1ull << (c & 63));
                }
            }
        }
    }
}

// pop the lowest set bit across a 192-bit value in 3 registers
__device__ __forceinline__ int pop_lowest(unsigned long long& w0,
                                          unsigned long long& w1,
                                          unsigned long long& w2) {
    if (w0) { int b = __ffsll((long long)w0) - 1; w0 &= w0 - 1; return b; }
    if (w1) { int b = __ffsll((long long)w1) - 1; w1 &= w1 - 1; return 64 + b; }
    {        int b = __ffsll((long long)w2) - 1; w2 &= w2 - 1; return 128 + b; }
}

__device__ __forceinline__ float sq_mod(float a, float b) {
    float x = a - b + PI_F;
    float m = x - TWOPI_F * floorf(x * INV_TWOPI_F);   // mod(x, 2pi) in [0,2pi)
    float d = m - PI_F;
    return d * d;
}

// ---------------- kernel 2: 4 lanes/row, uniform perm split ----------------
__global__ __launch_bounds__(FIN_THREADS)
void rmspe_finish(float* __restrict__ out) {
    __shared__ float s_warp[FIN_THREADS / 32];

    const int gtid = blockIdx.x * FIN_THREADS + threadIdx.x;
    const int row  = gtid >> 2;
    const int q    = gtid & 3;
    const int lane = threadIdx.x & 31;

    // ---- quad-broadcast loads (same sectors for all 4 lanes) ----
    unsigned long long* bp = &g_bits[row * 3];
    unsigned long long w0 = bp[0];
    unsigned long long w1 = bp[1];
    unsigned long long w2 = bp[2];
    float4 d = g_doa[row];

    if (q == 0) { bp[0] = 0ull; bp[1] = 0ull; bp[2] = 0ull; }  // replay reset

    // ---- uniform decode (identical in all lanes of the quad) ----
    int i0 = pop_lowest(w0, w1, w2);
    int i1 = pop_lowest(w0, w1, w2);
    int i2 = pop_lowest(w0, w1, w2);
    int i3 = pop_lowest(w0, w1, w2);

    float ang0 = ((float)i0 - 90.0f) * (PI_F / 180.0f);
    float ang1 = ((float)i1 - 90.0f) * (PI_F / 180.0f);
    float ang2 = ((float)i2 - 90.0f) * (PI_F / 180.0f);
    float ang3 = ((float)i3 - 90.0f) * (PI_F / 180.0f);

    // lane q owns column q for row 0; remaining columns rem[r] = r<q ? r : r+1
    float aq = (q == 0) ? ang0 : (q == 1) ? ang1 : (q == 2) ? ang2 : ang3;
    float a0 = (q > 0) ? ang0 : ang1;     // rem[0]
    float a1 = (q > 1) ? ang1 : ang2;     // rem[1]
    float a2 = (q > 2) ? ang2 : ang3;     // rem[2]

    // cost[0][q] + 3x3 cost of rows 1..3 vs remaining columns
    float c0  = sq_mod(d.x, aq);
    float c10 = sq_mod(d.y, a0), c11 = sq_mod(d.y, a1), c12 = sq_mod(d.y, a2);
    float c20 = sq_mod(d.z, a0), c21 = sq_mod(d.z, a1), c22 = sq_mod(d.z, a2);
    float c30 = sq_mod(d.w, a0), c31 = sq_mod(d.w, a1), c32 = sq_mod(d.w, a2);

    // 6 perms of the remaining 3 columns (identical pattern in every lane)
    float s0 = c10 + c21 + c32;
    float s1 = c10 + c22 + c31;
    float s2 = c11 + c20 + c32;
    float s3 = c11 + c22 + c30;
    float s4 = c12 + c20 + c31;
    float s5 = c12 + c21 + c30;
    float best = c0 + fminf(fminf(fminf(s0, s1), fminf(s2, s3)), fminf(s4, s5));

    // min across the quad -> full 24-perm min
    best = fminf(best, __shfl_xor_sync(0xffffffffu, best, 1));
    best = fminf(best, __shfl_xor_sync(0xffffffffu, best, 2));

    float rmse = (q == 0) ? sqrtf(best * 0.25f) : 0.0f;

    // ---- warp sum -> smem -> thread0 -> one double RED per block ----
    #pragma unroll
    for (int off = 16; off; off >>= 1)
        rmse += __shfl_down_sync(0xffffffffu, rmse, off);
    if (lane == 0) s_warp[threadIdx.x >> 5] = rmse;
    __syncthreads();

    if (threadIdx.x == 0) {
        float x = 0.0f;
        #pragma unroll
        for (int i = 0; i < FIN_THREADS / 32; i++) x += s_warp[i];
        atomicAdd(&g_acc, (double)x);
        __threadfence();
        unsigned prev = atomicAdd(&g_done, 1u);
        if (prev == FIN_BLOCKS - 1) {
            __threadfence();
            double total = *((volatile double*)&g_acc);
            out[0] = (float)(total / (double)BATCH);
            g_acc  = 0.0;     // deterministic state for next graph replay
            g_done = 0u;
        }
    }
}

extern "C" void kernel_launch(void* const* d_in, const int* in_sizes, int n_in,
                              void* d_out, int out_size) {
    const float* logits = (const float*)d_in[0];
    const int*   labels = (const int*)d_in[1];
    float* out = (float*)d_out;

    rmspe_scan<<<SCAN_BLOCKS, SCAN_THREADS>>>(logits, labels);
    rmspe_finish<<<FIN_BLOCKS, FIN_THREADS>>>(out);
}

// round 13
// speedup vs baseline: 1.1125x; 1.1125x over previous
#include <cuda_runtime.h>
#include <math.h>
#include <float.h>

// RMSPELoss R13: single kernel, ticket-tail fusion. Scan phase = pure R9
// stream (front-batched MLP=8, REDG bitmap). Blocks holding the LAST 512
// tickets spin until all scans done, then finish 1 row/thread on warm L2.
// Deadlock-safe: >=4 blocks/SM resident (592 slots) > 512 max spinners.

#define BATCH 131072
#define NC 181
#define PI_F 3.14159265358979323846f
#define TWOPI_F 6.283185307179586f
#define INV_TWOPI_F 0.15915494309189535f

#define THREADS 256
#define TOTAL_INT4 (BATCH * NC / 4)                    // 5,931,008
#define SCAN_UNROLL 8
#define NBLOCKS (TOTAL_INT4 / (THREADS * SCAN_UNROLL)) // 2896, exact
#define SCAN_STRIDE (NBLOCKS * THREADS)                // 741,376
#define FINISHERS 512                                  // 512*256 = BATCH rows

__device__ double   g_acc;     // zero-init; reset by last finisher each call
__device__ unsigned g_done;    // scan-complete ticket counter; reset each call
__device__ unsigned g_fin;     // finisher counter; reset each call
// 3 x 64-bit words per row (192 bits >= 181). Zero-init; finish re-zeroes
// every word it reads, so each graph replay starts clean.
__device__ unsigned long long g_bits[BATCH * 3];

// branchless pop-lowest across a 192-bit value held in 3 registers
__device__ __forceinline__ int pop_lowest_sel(unsigned long long& w0,
                                              unsigned long long& w1,
                                              unsigned long long& w2) {
    bool p0 = (w0 != 0ull);
    bool p1 = !p0 && (w1 != 0ull);
    bool p2 = !p0 && !p1;
    unsigned long long sel = p0 ? w0 : (p1 ? w1 : w2);
    int b = __ffsll((long long)sel) - 1 + (p0 ? 0 : (p1 ? 64 : 128));
    unsigned long long cl = sel & (sel - 1);
    w0 = p0 ? cl : w0;
    w1 = p1 ? cl : w1;
    w2 = p2 ? cl : w2;
    return b;
}

__global__ __launch_bounds__(THREADS, 4)
void rmspe_all(const float* __restrict__ logits, const int* __restrict__ labels,
               float* __restrict__ out) {
    __shared__ unsigned s_ticket;
    __shared__ float    s_warp[THREADS / 32];

    const int tid = threadIdx.x;
    const int t   = blockIdx.x * THREADS + tid;

    // ================= scan phase (pure stream, no barriers) =================
    {
        const int4* __restrict__ g4 = reinterpret_cast<const int4*>(labels);
        int4 v[SCAN_UNROLL];
        #pragma unroll
        for (int j = 0; j < SCAN_UNROLL; j++)
            v[j] = __ldcs(&g4[t + j * SCAN_STRIDE]);

        #pragma unroll
        for (int j = 0; j < SCAN_UNROLL; j++) {
            int4 x = v[j];
            if ((x.x | x.y | x.z | x.w) != 0) {          // rare (~8.5%)
                int linear = (t + j * SCAN_STRIDE) * 4;
                int vals[4] = {x.x, x.y, x.z, x.w};
                #pragma unroll
                for (int k = 0; k < 4; k++) {
                    if (vals[k] == 1) {
                        int l = linear + k;
                        int r = l / NC;                  // mul-shift by constant
                        int c = l - r * NC;
                        // result unused -> REDG (fire-and-forget)
                        atomicOr(&g_bits[r * 3 + (c >> 6)], 1ull << (c & 63));
                    }
                }
            }
        }
    }

    // ================= ticket: release my REDs, count completion =============
    __threadfence();                 // make this thread's REDs visible
    __syncthreads();                 // whole block's scan done
    if (tid == 0) s_ticket = atomicAdd(&g_done, 1u);
    __syncthreads();
    const unsigned ticket = s_ticket;

    if (ticket < (unsigned)(NBLOCKS - FINISHERS)) return;   // non-participant

    // ================= wait for ALL scan slices =============================
    if (tid == 0) {
        while (*((volatile unsigned*)&g_done) != (unsigned)NBLOCKS)
            __nanosleep(64);
    }
    __syncthreads();
    __threadfence();                 // acquire: bitmap fully visible

    // ================= finish: one row per thread ===========================
    const int row = (int)(ticket - (NBLOCKS - FINISHERS)) * THREADS + tid;

    unsigned long long* bp = &g_bits[row * 3];
    unsigned long long w0 = bp[0];
    unsigned long long w1 = bp[1];
    unsigned long long w2 = bp[2];
    const float* lp = logits + (long)row * NC;
    float d0 = __ldg(lp), d1 = __ldg(lp + 1), d2 = __ldg(lp + 2), d3 = __ldg(lp + 3);

    bp[0] = 0ull; bp[1] = 0ull; bp[2] = 0ull;   // reset for next graph replay

    int i0 = pop_lowest_sel(w0, w1, w2);
    int i1 = pop_lowest_sel(w0, w1, w2);
    int i2 = pop_lowest_sel(w0, w1, w2);
    int i3 = pop_lowest_sel(w0, w1, w2);

    float ang[4];
    ang[0] = ((float)i0 - 90.0f) * (PI_F / 180.0f);
    ang[1] = ((float)i1 - 90.0f) * (PI_F / 180.0f);
    ang[2] = ((float)i2 - 90.0f) * (PI_F / 180.0f);
    ang[3] = ((float)i3 - 90.0f) * (PI_F / 180.0f);
    float doa[4] = {d0, d1, d2, d3};

    float cost[4][4];
    #pragma unroll
    for (int i = 0; i < 4; i++) {
        #pragma unroll
        for (int j = 0; j < 4; j++) {
            float x = doa[i] - ang[j] + PI_F;
            float m = x - TWOPI_F * floorf(x * INV_TWOPI_F);  // mod in [0,2pi)
            float dd = m - PI_F;
            cost[i][j] = dd * dd;
        }
    }

    float best = FLT_MAX;
    #define P4(a,b,c,e) best = fminf(best, cost[0][a] + cost[1][b] + cost[2][c] + cost[3][e]);
    P4(0,1,2,3) P4(0,1,3,2) P4(0,2,1,3) P4(0,2,3,1) P4(0,3,1,2) P4(0,3,2,1)
    P4(1,0,2,3) P4(1,0,3,2) P4(1,2,0,3) P4(1,2,3,0) P4(1,3,0,2) P4(1,3,2,0)
    P4(2,0,1,3) P4(2,0,3,1) P4(2,1,0,3) P4(2,1,3,0) P4(2,3,0,1) P4(2,3,1,0)
    P4(3,0,1,2) P4(3,0,2,1) P4(3,1,0,2) P4(3,1,2,0) P4(3,2,0,1) P4(3,2,1,0)
    #undef P4

    float rmse = sqrtf(best * 0.25f);

    // ---- block reduce -> one double RED; last finisher writes + resets ----
    #pragma unroll
    for (int off = 16; off; off >>= 1)
        rmse += __shfl_down_sync(0xffffffffu, rmse, off);
    if ((tid & 31) == 0) s_warp[tid >> 5] = rmse;
    __syncthreads();

    if (tid == 0) {
        float x = 0.0f;
        #pragma unroll
        for (int i = 0; i < THREADS / 32; i++) x += s_warp[i];
        atomicAdd(&g_acc, (double)x);
        __threadfence();
        unsigned prev = atomicAdd(&g_fin, 1u);
        if (prev == FINISHERS - 1) {
            __threadfence();
            double total = *((volatile double*)&g_acc);
            out[0] = (float)(total / (double)BATCH);
            g_acc  = 0.0;    // deterministic state for next graph replay
            g_done = 0u;
            g_fin  = 0u;
        }
    }
}

extern "C" void kernel_launch(void* const* d_in, const int* in_sizes, int n_in,
                              void* d_out, int out_size) {
    const float* logits = (const float*)d_in[0];
    const int*   labels = (const int*)d_in[1];
    float* out = (float*)d_out;

    rmspe_all<<<NBLOCKS, THREADS>>>(logits, labels, out);
}

// round 16
// speedup vs baseline: 1.2373x; 1.1122x over previous
#include <cuda_runtime.h>
#include <math.h>
#include <float.h>

// RMSPELoss R14: warp-autonomous fused kernel. Each warp owns 4 rows
// (181 int4, 16B-aligned): 6 front-batched label LDG.128 + logits scalar
// (MLP=7), filter hits into per-warp smem slots, __syncwarp only, lanes 0-3
// finish the 4 rows in registers. No block barrier between load and consume.

#define BATCH 131072
#define NC 181
#define PI_F 3.14159265358979323846f
#define TWOPI_F 6.283185307179586f
#define INV_TWOPI_F 0.15915494309189535f

#define THREADS 256
#define WARPS (THREADS / 32)
#define ROWS_PER_WARP 4
#define ROWS_PER_BLOCK (WARPS * ROWS_PER_WARP)        // 32
#define NBLOCKS (BATCH / ROWS_PER_BLOCK)              // 4096
#define INT4_PER_WARP 181                             // 4 rows * 181 ints / 4

__device__ double   g_acc;    // zero-init; reset by last block each call
__device__ unsigned g_done;   // zero-init; reset by last block each call

__global__ __launch_bounds__(THREADS)
void rmspe_warp(const float* __restrict__ logits, const int* __restrict__ labels,
                float* __restrict__ out) {
    __shared__ int   s_cnt[WARPS][4];
    __shared__ int   s_idx[WARPS][4][4];
    __shared__ float s_part[WARPS];

    const int tid  = threadIdx.x;
    const int lane = tid & 31;
    const int w    = tid >> 5;
    const long rowg0 = (long)blockIdx.x * ROWS_PER_BLOCK + w * ROWS_PER_WARP;

    // ---- per-warp init + ONE latency wave (6 label int4 + logits scalar) ----
    if (lane < 4) s_cnt[w][lane] = 0;

    const int4* __restrict__ g4 = reinterpret_cast<const int4*>(labels)
                                + ((long)blockIdx.x * (ROWS_PER_BLOCK * NC / 4)
                                   + w * INT4_PER_WARP);
    int4 v[6];
    #pragma unroll
    for (int j = 0; j < 6; j++) {
        int i = lane + 32 * j;
        v[j] = make_int4(0, 0, 0, 0);
        if (i < INT4_PER_WARP) v[j] = __ldcs(&g4[i]);   // front-batched
    }
    float f = 0.0f;
    if (lane < 16)                                      // 4 rows x 4 scalars
        f = __ldg(&logits[(rowg0 + (lane >> 2)) * NC + (lane & 3)]);
    __syncwarp();                                       // s_cnt zero visible

    // ---- filter the warp's 724 ints into per-warp slots (smem ATOMS) ----
    #pragma unroll
    for (int j = 0; j < 6; j++) {
        int4 x = v[j];
        if ((x.x | x.y | x.z | x.w) != 0) {             // rare
            int linear = (lane + 32 * j) * 4;           // 0..723
            int vals[4] = {x.x, x.y, x.z, x.w};
            #pragma unroll
            for (int k = 0; k < 4; k++) {
                if (vals[k] == 1) {
                    int l = linear + k;
                    int r = l / NC;                     // local row 0..3
                    int c = l - r * NC;
                    int p = atomicAdd(&s_cnt[w][r], 1);
                    if (p < 4) s_idx[w][r][p] = c;
                }
            }
        }
    }
    __syncwarp();

    // ---- doa broadcast (convergent shuffles), lanes 0-3 finish 4 rows ----
    int rsel = lane & 3;
    float doa[4];
    #pragma unroll
    for (int k = 0; k < 4; k++)
        doa[k] = __shfl_sync(0xffffffffu, f, rsel * 4 + k);

    float rmse = 0.0f;
    if (lane < 4) {
        float ang[4];
        #pragma unroll
        for (int k = 0; k < 4; k++)
            ang[k] = ((float)s_idx[w][lane][k] - 90.0f) * (PI_F / 180.0f);

        float cost[4][4];
        #pragma unroll
        for (int i = 0; i < 4; i++) {
            #pragma unroll
            for (int j = 0; j < 4; j++) {
                float x = doa[i] - ang[j] + PI_F;
                float m = x - TWOPI_F * floorf(x * INV_TWOPI_F);  // mod [0,2pi)
                float d = m - PI_F;
                cost[i][j] = d * d;
            }
        }

        float best = FLT_MAX;
        #define P4(a,b,c,e) best = fminf(best, cost[0][a] + cost[1][b] + cost[2][c] + cost[3][e]);
        P4(0,1,2,3) P4(0,1,3,2) P4(0,2,1,3) P4(0,2,3,1) P4(0,3,1,2) P4(0,3,2,1)
        P4(1,0,2,3) P4(1,0,3,2) P4(1,2,0,3) P4(1,2,3,0) P4(1,3,0,2) P4(1,3,2,0)
        P4(2,0,1,3) P4(2,0,3,1) P4(2,1,0,3) P4(2,1,3,0) P4(2,3,0,1) P4(2,3,1,0)
        P4(3,0,1,2) P4(3,0,2,1) P4(3,1,0,2) P4(3,1,2,0) P4(3,2,0,1) P4(3,2,1,0)
        #undef P4

        rmse = sqrtf(best * 0.25f);
    }

    // sum the 4 row results (lanes >=4 contribute 0)
    #pragma unroll
    for (int off = 16; off; off >>= 1)
        rmse += __shfl_down_sync(0xffffffffu, rmse, off);
    if (lane == 0) s_part[w] = rmse;

    // ---- single trailing block barrier + 1 double RED + epilogue ----
    __syncthreads();
    if (tid == 0) {
        float x = 0.0f;
        #pragma unroll
        for (int i = 0; i < WARPS; i++) x += s_part[i];
        atomicAdd(&g_acc, (double)x);
        __threadfence();
        unsigned prev = atomicAdd(&g_done, 1u);
        if (prev == NBLOCKS - 1) {
            __threadfence();
            double total = *((volatile double*)&g_acc);
            out[0] = (float)(total / (double)BATCH);
            g_acc  = 0.0;    // deterministic state for next graph replay
            g_done = 0u;
        }
    }
}

extern "C" void kernel_launch(void* const* d_in, const int* in_sizes, int n_in,
                              void* d_out, int out_size) {
    const float* logits = (const float*)d_in[0];
    const int*   labels = (const int*)d_in[1];
    float* out = (float*)d_out;

    rmspe_warp<<<NBLOCKS, THREADS>>>(logits, labels, out);
}